// round 4
// baseline (speedup 1.0000x reference)
#include <cuda_runtime.h>
#include <math.h>

// Problem shape (fixed by setup_inputs)
#define BH     64
#define MSEQ   1024
#define DIM    64
#define LSPAN  1024

#define BM     64        // query rows per CTA
#define BL     64        // l-tile width
#define KROWS  128       // BM + BL band rows per tile

#define QT_STRIDE 68
#define KT_STRIDE 132
#define PS_STRIDE 68
#define WT_STRIDE 68

// smem layout (floats):
//  Qt : 64 * 68            = 4352
//  KV : max(64*132, 128*64)= 8448   (Kt transposed  /  Vs row-major union)
//  Ps : 64 * 68            = 4352
//  Wt : 128 * 68           = 8704   (skewed exp-weights, transposed [k][i])
#define SMEM_FLOATS (4352 + 8448 + 4352 + 8704)

__global__ void __launch_bounds__(256, 2) seqattn_kernel(
    const float* __restrict__ Q,   // [BH, MSEQ, DIM]
    const float* __restrict__ K,   // [BH, MSEQ+LSPAN, DIM]
    const float* __restrict__ V,   // [BH, MSEQ+LSPAN, DIM]
    const float* __restrict__ P,   // [1, DIM, LSPAN]
    float* __restrict__ O)         // [BH, MSEQ, DIM]
{
    extern __shared__ float smem[];
    float* Qt = smem;                       // [64][QT_STRIDE]
    float* KV = Qt + 64 * QT_STRIDE;        // union: Kt [64][KT_STRIDE] / Vs [128][64]
    float* Ps = KV + 8448;                  // [64][PS_STRIDE]
    float* Wt = Ps + 64 * PS_STRIDE;        // [128][WT_STRIDE]

    const int tid = threadIdx.x;
    const int tx  = tid & 15;               // 16 cols of thread grid
    const int ty  = tid >> 4;               // 16 rows of thread grid
    const int bh  = blockIdx.y;
    const int m0  = blockIdx.x * BM;

    const float* Qg = Q + ((size_t)bh * MSEQ + m0) * DIM;
    const float* Kg = K + (size_t)bh * (MSEQ + LSPAN) * DIM;
    const float* Vg = V + (size_t)bh * (MSEQ + LSPAN) * DIM;

    // ---- load Q transposed: Qt[d][i] ----
    {
        const int j0 = tid >> 6;            // 0..3
        const int d  = tid & 63;
        #pragma unroll
        for (int p = 0; p < 16; p++) {
            int row = p * 4 + j0;
            Qt[d * QT_STRIDE + row] = Qg[row * DIM + d];
        }
    }

    float acc_o[4][4];
    float m_run[4], l_run[4];
    #pragma unroll
    for (int a = 0; a < 4; a++) {
        m_run[a] = -INFINITY; l_run[a] = 0.f;
        #pragma unroll
        for (int b = 0; b < 4; b++) acc_o[a][b] = 0.f;
    }

    for (int lt = 0; lt < LSPAN / BL; lt++) {
        __syncthreads();   // prev tile's PV done -> KV/Wt reusable

        // ---- load K band transposed: Kt[d][j], j in [0,128) ----
        {
            const int j0 = tid >> 6;
            const int d  = tid & 63;
            const float* src = Kg + (size_t)(m0 + lt * BL) * DIM + d;
            #pragma unroll
            for (int p = 0; p < 32; p++) {
                int j = p * 4 + j0;
                KV[d * KT_STRIDE + j] = src[(size_t)j * DIM];
            }
        }
        // ---- load Ps[d][l'] (float4) ----
        {
            const int d0 = tid >> 4;        // 0..15
            const int l4 = tid & 15;
            #pragma unroll
            for (int p = 0; p < 4; p++) {
                int dd = p * 16 + d0;
                float4 v = *(const float4*)(P + (size_t)dd * LSPAN + lt * BL + l4 * 4);
                *(float4*)(Ps + dd * PS_STRIDE + l4 * 4) = v;
            }
        }
        __syncthreads();

        // ---- S tile: s[i][l'] = sum_d q[i][d] * (k[i+l'][d] + p[d][l']) ----
        float acc[4][4];
        #pragma unroll
        for (int a = 0; a < 4; a++)
            #pragma unroll
            for (int b = 0; b < 4; b++) acc[a][b] = 0.f;

        const int kbase = 4 * (tx + ty);
        #pragma unroll 4
        for (int d = 0; d < DIM; d++) {
            float4 qv = *(const float4*)(Qt + d * QT_STRIDE + ty * 4);
            float4 pv = *(const float4*)(Ps + d * PS_STRIDE + tx * 4);
            float4 k0 = *(const float4*)(KV + d * KT_STRIDE + kbase);
            float4 k1 = *(const float4*)(KV + d * KT_STRIDE + kbase + 4);
            float kk[8] = {k0.x,k0.y,k0.z,k0.w,k1.x,k1.y,k1.z,k1.w};
            float qq[4] = {qv.x,qv.y,qv.z,qv.w};
            float pp[4] = {pv.x,pv.y,pv.z,pv.w};
            #pragma unroll
            for (int a = 0; a < 4; a++)
                #pragma unroll
                for (int b = 0; b < 4; b++)
                    acc[a][b] = fmaf(qq[a], kk[a + b] + pp[b], acc[a][b]);
        }

        // ---- online softmax + write skewed exp weights ----
        #pragma unroll
        for (int a = 0; a < 4; a++) {
            float tmax = acc[a][0];
            #pragma unroll
            for (int b = 1; b < 4; b++) tmax = fmaxf(tmax, acc[a][b]);
            tmax *= 0.125f;   // 1/sqrt(64)
            #pragma unroll
            for (int mm = 1; mm <= 8; mm <<= 1)
                tmax = fmaxf(tmax, __shfl_xor_sync(0xffffffffu, tmax, mm));
            float mnew = fmaxf(m_run[a], tmax);

            float pvals[4];
            float rsum = 0.f;
            #pragma unroll
            for (int b = 0; b < 4; b++) {
                pvals[b] = __expf(fmaf(acc[a][b], 0.125f, -mnew));
                rsum += pvals[b];
            }
            #pragma unroll
            for (int mm = 1; mm <= 8; mm <<= 1)
                rsum += __shfl_xor_sync(0xffffffffu, rsum, mm);

            float c = __expf(m_run[a] - mnew);
            l_run[a] = l_run[a] * c + rsum;
            m_run[a] = mnew;
            #pragma unroll
            for (int b = 0; b < 4; b++) acc_o[a][b] *= c;

            // skewed write: Wt[k = i + l'][i]; complement slots -> 0
            const int i = ty * 4 + a;
            #pragma unroll
            for (int b = 0; b < 4; b++) {
                int k = i + tx * 4 + b;
                Wt[k * WT_STRIDE + i] = pvals[b];
                Wt[((k + 64) & 127) * WT_STRIDE + i] = 0.f;
            }
        }
        __syncthreads();

        // ---- load V band into KV union: Vs[j][d] ----
        {
            const int j0 = tid >> 4;        // 0..15
            const int d4 = tid & 15;
            const float* src = Vg + (size_t)(m0 + lt * BL) * DIM;
            #pragma unroll
            for (int p = 0; p < 8; p++) {
                int jj = p * 16 + j0;
                float4 v = *(const float4*)(src + (size_t)jj * DIM + d4 * 4);
                *(float4*)(KV + jj * 64 + d4 * 4) = v;
            }
        }
        __syncthreads();

        // ---- PV: out[i][d] += sum_k Wt[k][i] * Vs[k][d], banded k-window ----
        {
            const int kstart = ty * 4;      // rows i in [ty*4, ty*4+4) need k in [ty*4, ty*4+68)
            #pragma unroll 4
            for (int ki = 0; ki < 68; ki++) {
                int k = kstart + ki;
                float4 w = *(const float4*)(Wt + k * WT_STRIDE + ty * 4);
                float4 v = *(const float4*)(KV + k * 64 + tx * 4);
                float ww[4] = {w.x,w.y,w.z,w.w};
                float vv[4] = {v.x,v.y,v.z,v.w};
                #pragma unroll
                for (int a = 0; a < 4; a++)
                    #pragma unroll
                    for (int b = 0; b < 4; b++)
                        acc_o[a][b] = fmaf(ww[a], vv[b], acc_o[a][b]);
            }
        }
    }

    // ---- epilogue: normalize and store ----
    #pragma unroll
    for (int a = 0; a < 4; a++) {
        float inv = 1.f / l_run[a];
        int i = ty * 4 + a;
        float4 o;
        o.x = acc_o[a][0] * inv;
        o.y = acc_o[a][1] * inv;
        o.z = acc_o[a][2] * inv;
        o.w = acc_o[a][3] * inv;
        *(float4*)(O + ((size_t)bh * MSEQ + m0 + i) * DIM + tx * 4) = o;
    }
}

extern "C" void kernel_launch(void* const* d_in, const int* in_sizes, int n_in,
                              void* d_out, int out_size) {
    const float* Q = (const float*)d_in[0];
    const float* K = (const float*)d_in[1];
    const float* V = (const float*)d_in[2];
    const float* P = (const float*)d_in[3];
    float* O = (float*)d_out;

    (void)n_in; (void)in_sizes; (void)out_size;

    const size_t smem_bytes = SMEM_FLOATS * sizeof(float);  // 103424 B
    cudaFuncSetAttribute(seqattn_kernel,
                         cudaFuncAttributeMaxDynamicSharedMemorySize,
                         (int)smem_bytes);

    dim3 grid(MSEQ / BM, BH);   // (16, 64)
    seqattn_kernel<<<grid, 256, smem_bytes>>>(Q, K, V, P, O);
}

// round 5
// speedup vs baseline: 1.0540x; 1.0540x over previous
#include <cuda_runtime.h>
#include <math.h>

// Problem shape (fixed by setup_inputs)
#define BH     64
#define MSEQ   1024
#define DIM    64
#define LSPAN  1024

#define BM     64        // query rows per CTA
#define BL     64        // l-tile width
#define KROWS  128       // BM + BL band rows per tile

#define QT_STRIDE 68
#define KT_STRIDE 132
#define PS_STRIDE 68
#define WT_STRIDE 68

// smem layout (floats):
//  Qt : 64 * 68            = 4352
//  KV : max(64*132, 128*64)= 8448   (Kt transposed  /  Vs row-major union)
//  Ps : 64 * 68            = 4352
//  Wt : 128 * 68           = 8704   (skewed exp-weights, transposed [k][i])
#define SMEM_FLOATS (4352 + 8448 + 4352 + 8704)

__global__ void __launch_bounds__(256, 2) seqattn_kernel(
    const float* __restrict__ Q,   // [BH, MSEQ, DIM]
    const float* __restrict__ K,   // [BH, MSEQ+LSPAN, DIM]
    const float* __restrict__ V,   // [BH, MSEQ+LSPAN, DIM]
    const float* __restrict__ P,   // [1, DIM, LSPAN]
    float* __restrict__ O)         // [BH, MSEQ, DIM]
{
    extern __shared__ float smem[];
    float* Qt = smem;                       // [64][QT_STRIDE]
    float* KV = Qt + 64 * QT_STRIDE;        // union: Kt [64][KT_STRIDE] / Vs [128][64]
    float* Ps = KV + 8448;                  // [64][PS_STRIDE]
    float* Wt = Ps + 64 * PS_STRIDE;        // [128][WT_STRIDE]

    const int tid = threadIdx.x;
    const int tx  = tid & 15;               // 16 cols of thread grid
    const int ty  = tid >> 4;               // 16 rows of thread grid
    const int bh  = blockIdx.y;
    const int m0  = blockIdx.x * BM;

    const float* Qg = Q + ((size_t)bh * MSEQ + m0) * DIM;
    const float* Kg = K + (size_t)bh * (MSEQ + LSPAN) * DIM;
    const float* Vg = V + (size_t)bh * (MSEQ + LSPAN) * DIM;

    // ---- load Q transposed: Qt[d][i] ----
    {
        const int j0 = tid >> 6;            // 0..3
        const int d  = tid & 63;
        #pragma unroll
        for (int p = 0; p < 16; p++) {
            int row = p * 4 + j0;
            Qt[d * QT_STRIDE + row] = Qg[row * DIM + d];
        }
    }

    float acc_o[4][4];
    float m_run[4], l_run[4];
    #pragma unroll
    for (int a = 0; a < 4; a++) {
        m_run[a] = -INFINITY; l_run[a] = 0.f;
        #pragma unroll
        for (int b = 0; b < 4; b++) acc_o[a][b] = 0.f;
    }

    for (int lt = 0; lt < LSPAN / BL; lt++) {
        __syncthreads();   // prev tile's PV done -> KV/Wt reusable

        // ---- load K band transposed: Kt[d][j], j in [0,128) ----
        {
            const int j0 = tid >> 6;
            const int d  = tid & 63;
            const float* src = Kg + (size_t)(m0 + lt * BL) * DIM + d;
            #pragma unroll
            for (int p = 0; p < 32; p++) {
                int j = p * 4 + j0;
                KV[d * KT_STRIDE + j] = src[(size_t)j * DIM];
            }
        }
        // ---- load Ps[d][l'] (float4) ----
        {
            const int d0 = tid >> 4;        // 0..15
            const int l4 = tid & 15;
            #pragma unroll
            for (int p = 0; p < 4; p++) {
                int dd = p * 16 + d0;
                float4 v = *(const float4*)(P + (size_t)dd * LSPAN + lt * BL + l4 * 4);
                *(float4*)(Ps + dd * PS_STRIDE + l4 * 4) = v;
            }
        }
        __syncthreads();

        // ---- S tile: s[i][l'] = sum_d q[i][d] * (k[i+l'][d] + p[d][l']) ----
        float acc[4][4];
        #pragma unroll
        for (int a = 0; a < 4; a++)
            #pragma unroll
            for (int b = 0; b < 4; b++) acc[a][b] = 0.f;

        const int kbase = 4 * (tx + ty);
        #pragma unroll 4
        for (int d = 0; d < DIM; d++) {
            float4 qv = *(const float4*)(Qt + d * QT_STRIDE + ty * 4);
            float4 pv = *(const float4*)(Ps + d * PS_STRIDE + tx * 4);
            float4 k0 = *(const float4*)(KV + d * KT_STRIDE + kbase);
            float4 k1 = *(const float4*)(KV + d * KT_STRIDE + kbase + 4);
            float kk[8] = {k0.x,k0.y,k0.z,k0.w,k1.x,k1.y,k1.z,k1.w};
            float qq[4] = {qv.x,qv.y,qv.z,qv.w};
            float pp[4] = {pv.x,pv.y,pv.z,pv.w};
            #pragma unroll
            for (int a = 0; a < 4; a++)
                #pragma unroll
                for (int b = 0; b < 4; b++)
                    acc[a][b] = fmaf(qq[a], kk[a + b] + pp[b], acc[a][b]);
        }

        // ---- online softmax + write skewed exp weights ----
        #pragma unroll
        for (int a = 0; a < 4; a++) {
            float tmax = acc[a][0];
            #pragma unroll
            for (int b = 1; b < 4; b++) tmax = fmaxf(tmax, acc[a][b]);
            tmax *= 0.125f;   // 1/sqrt(64)
            #pragma unroll
            for (int mm = 1; mm <= 8; mm <<= 1)
                tmax = fmaxf(tmax, __shfl_xor_sync(0xffffffffu, tmax, mm));
            float mnew = fmaxf(m_run[a], tmax);

            float pvals[4];
            float rsum = 0.f;
            #pragma unroll
            for (int b = 0; b < 4; b++) {
                pvals[b] = __expf(fmaf(acc[a][b], 0.125f, -mnew));
                rsum += pvals[b];
            }
            #pragma unroll
            for (int mm = 1; mm <= 8; mm <<= 1)
                rsum += __shfl_xor_sync(0xffffffffu, rsum, mm);

            float c = __expf(m_run[a] - mnew);
            l_run[a] = l_run[a] * c + rsum;
            m_run[a] = mnew;
            #pragma unroll
            for (int b = 0; b < 4; b++) acc_o[a][b] *= c;

            // skewed write: Wt[k = i + l'][i]; complement slots -> 0
            const int i = ty * 4 + a;
            #pragma unroll
            for (int b = 0; b < 4; b++) {
                int k = i + tx * 4 + b;
                Wt[k * WT_STRIDE + i] = pvals[b];
                Wt[((k + 64) & 127) * WT_STRIDE + i] = 0.f;
            }
        }
        __syncthreads();

        // ---- load V band into KV union: Vs[j][d] ----
        {
            const int j0 = tid >> 4;        // 0..15
            const int d4 = tid & 15;
            const float* src = Vg + (size_t)(m0 + lt * BL) * DIM;
            #pragma unroll
            for (int p = 0; p < 8; p++) {
                int jj = p * 16 + j0;
                float4 v = *(const float4*)(src + (size_t)jj * DIM + d4 * 4);
                *(float4*)(KV + jj * 64 + d4 * 4) = v;
            }
        }
        __syncthreads();

        // ---- PV: out[i][d] += sum_k Wt[k][i] * Vs[k][d], banded k-window ----
        {
            const int kstart = ty * 4;      // rows i in [ty*4, ty*4+4) need k in [ty*4, ty*4+68)
            #pragma unroll 4
            for (int ki = 0; ki < 68; ki++) {
                int k = kstart + ki;
                float4 w = *(const float4*)(Wt + k * WT_STRIDE + ty * 4);
                float4 v = *(const float4*)(KV + k * 64 + tx * 4);
                float ww[4] = {w.x,w.y,w.z,w.w};
                float vv[4] = {v.x,v.y,v.z,v.w};
                #pragma unroll
                for (int a = 0; a < 4; a++)
                    #pragma unroll
                    for (int b = 0; b < 4; b++)
                        acc_o[a][b] = fmaf(ww[a], vv[b], acc_o[a][b]);
            }
        }
    }

    // ---- epilogue: normalize and store ----
    #pragma unroll
    for (int a = 0; a < 4; a++) {
        float inv = 1.f / l_run[a];
        int i = ty * 4 + a;
        float4 o;
        o.x = acc_o[a][0] * inv;
        o.y = acc_o[a][1] * inv;
        o.z = acc_o[a][2] * inv;
        o.w = acc_o[a][3] * inv;
        *(float4*)(O + ((size_t)bh * MSEQ + m0 + i) * DIM + tx * 4) = o;
    }
}

extern "C" void kernel_launch(void* const* d_in, const int* in_sizes, int n_in,
                              void* d_out, int out_size) {
    const float* Q = (const float*)d_in[0];
    const float* K = (const float*)d_in[1];
    const float* V = (const float*)d_in[2];
    const float* P = (const float*)d_in[3];
    float* O = (float*)d_out;

    (void)n_in; (void)in_sizes; (void)out_size;

    const size_t smem_bytes = SMEM_FLOATS * sizeof(float);  // 103424 B
    cudaFuncSetAttribute(seqattn_kernel,
                         cudaFuncAttributeMaxDynamicSharedMemorySize,
                         (int)smem_bytes);

    dim3 grid(MSEQ / BM, BH);   // (16, 64)
    seqattn_kernel<<<grid, 256, smem_bytes>>>(Q, K, V, P, O);
}

// round 7
// speedup vs baseline: 1.3556x; 1.2862x over previous
#include <cuda_runtime.h>
#include <cstdint>
#include <math.h>

// -------- problem shape --------
#define BHN    64
#define MSEQ   1024
#define DIMN   64
#define LSPAN  1024
#define BM     64          // query rows per CTA
#define BL     128         // l-tile width
#define RW     192         // band rect width = BM + BL
#define NCAT   320         // RW + BL (concatenated B)
#define NT     (LSPAN / BL)

// -------- smem float offsets --------
// Qs  [64][68]   = 4352
// Bc  [320][68]  = 21760   (K band rows 0..191, P^T rows 192..319)
// Ps  overlay of Bc: [64][132] pos scores (raw fp32)
// Vs  [192][72]  = 13824
// Ws  [64][196]  = 12544   (skewed exp weights, tf32)
// Rs  [64]       rowsums
#define QS_OFF 0
#define BC_OFF 4352
#define PS_OFF 4352
#define VS_OFF 26112
#define WS_OFF 39936
#define RS_OFF 52480
#define SMEM_FLOATS 52544   // 210176 bytes

__device__ __forceinline__ uint32_t f2tf(float x) {
    uint32_t u;
    asm("cvt.rna.tf32.f32 %0, %1;" : "=r"(u) : "f"(x));
    return u;
}

__device__ __forceinline__ void mma_tf32(float c[4], const uint32_t a[4], const uint32_t b[2]) {
    asm volatile(
        "mma.sync.aligned.m16n8k8.row.col.f32.tf32.tf32.f32 "
        "{%0,%1,%2,%3}, {%4,%5,%6,%7}, {%8,%9}, {%0,%1,%2,%3};"
        : "+f"(c[0]), "+f"(c[1]), "+f"(c[2]), "+f"(c[3])
        : "r"(a[0]), "r"(a[1]), "r"(a[2]), "r"(a[3]), "r"(b[0]), "r"(b[1]));
}

__global__ void __launch_bounds__(256, 1) seqattn_mma_kernel(
    const float* __restrict__ Q,   // [BH, M, D]
    const float* __restrict__ K,   // [BH, M+L, D]
    const float* __restrict__ V,   // [BH, M+L, D]
    const float* __restrict__ P,   // [D, L]
    float* __restrict__ O)         // [BH, M, D]
{
    extern __shared__ float sm[];
    float*    Qs  = sm + QS_OFF;
    float*    Bc  = sm + BC_OFF;
    float*    Ps  = sm + PS_OFF;
    float*    Vs  = sm + VS_OFF;
    float*    Ws  = sm + WS_OFF;
    float*    Rs  = sm + RS_OFF;
    const uint32_t* Qsu = (const uint32_t*)Qs;
    const uint32_t* Bcu = (const uint32_t*)Bc;
    const uint32_t* Vsu = (const uint32_t*)Vs;
    const uint32_t* Wsu = (const uint32_t*)Ws;

    const int tid  = threadIdx.x;
    const int w    = tid >> 5;
    const int lane = tid & 31;
    const int wm   = w >> 2;        // 0..1  (m group of 32 rows)
    const int wn   = w & 3;         // 0..3  (n group of 80 cols)
    const int g    = lane >> 2;     // groupID
    const int tig  = lane & 3;      // thread-in-group

    const int bh = blockIdx.y;
    const int m0 = blockIdx.x * BM;

    const float* Qg = Q + ((size_t)bh * MSEQ + m0) * DIMN;
    const float* Kg = K + (size_t)bh * (MSEQ + LSPAN) * DIMN;
    const float* Vg = V + (size_t)bh * (MSEQ + LSPAN) * DIMN;

    // ---- load Q once (tf32-rounded), stride 68 ----
    #pragma unroll
    for (int p = 0; p < 4; p++) {
        int idx = p * 256 + tid;
        int r = idx >> 4, c4 = idx & 15;
        float4 v = *(const float4*)(Qg + (size_t)r * DIMN + c4 * 4);
        uint4 u = make_uint4(f2tf(v.x), f2tf(v.y), f2tf(v.z), f2tf(v.w));
        *(uint4*)(Qs + r * 68 + c4 * 4) = u;
    }
    if (tid < 64) Rs[tid] = 0.f;

    float cO[2][2][4];
    #pragma unroll
    for (int a = 0; a < 2; a++)
        #pragma unroll
        for (int b = 0; b < 2; b++)
            #pragma unroll
            for (int c = 0; c < 4; c++) cO[a][b][c] = 0.f;

    float rsv[4] = {0.f, 0.f, 0.f, 0.f};   // per-thread row sums (rows: wm*32+mb*16+g+8h)

    for (int lt = 0; lt < NT; lt++) {
        __syncthreads();   // prev tile fully consumed

        const int jg0 = m0 + lt * BL;

        // ---- K band -> Bc rows [0,192) ----
        #pragma unroll
        for (int p = 0; p < 12; p++) {
            int idx = p * 256 + tid;
            int r = idx >> 4, c4 = idx & 15;
            float4 v = *(const float4*)(Kg + (size_t)(jg0 + r) * DIMN + c4 * 4);
            uint4 u = make_uint4(f2tf(v.x), f2tf(v.y), f2tf(v.z), f2tf(v.w));
            *(uint4*)(Bc + r * 68 + c4 * 4) = u;
        }
        // ---- P^T -> Bc rows [192,320): Bc[192+l'][d] = P[d][lt*128+l'] ----
        {
            int d  = tid >> 2;
            int l4b = tid & 3;
            #pragma unroll
            for (int p = 0; p < 8; p++) {
                int l4 = p * 4 + l4b;
                float4 v = *(const float4*)(P + (size_t)d * LSPAN + lt * BL + l4 * 4);
                float vv[4] = {v.x, v.y, v.z, v.w};
                #pragma unroll
                for (int u = 0; u < 4; u++)
                    Bc[(192 + l4 * 4 + u) * 68 + d] = __uint_as_float(f2tf(vv[u]));
            }
        }
        // ---- V band -> Vs [192][72] ----
        #pragma unroll
        for (int p = 0; p < 12; p++) {
            int idx = p * 256 + tid;
            int r = idx >> 4, c4 = idx & 15;
            float4 v = *(const float4*)(Vg + (size_t)(jg0 + r) * DIMN + c4 * 4);
            uint4 u = make_uint4(f2tf(v.x), f2tf(v.y), f2tf(v.z), f2tf(v.w));
            *(uint4*)(Vs + r * 72 + c4 * 4) = u;
        }
        __syncthreads();

        // ---- S_cat GEMM: [64 x 320] = Q[64x64] * Bc^T ----
        float cS[2][10][4];
        #pragma unroll
        for (int mb = 0; mb < 2; mb++)
            #pragma unroll
            for (int nb = 0; nb < 10; nb++)
                #pragma unroll
                for (int c = 0; c < 4; c++) cS[mb][nb][c] = 0.f;

        #pragma unroll
        for (int ks = 0; ks < 8; ks++) {
            uint32_t afr[2][4];
            const int col = ks * 8 + tig;
            #pragma unroll
            for (int mb = 0; mb < 2; mb++) {
                int row = wm * 32 + mb * 16 + g;
                afr[mb][0] = Qsu[row * 68 + col];
                afr[mb][1] = Qsu[(row + 8) * 68 + col];
                afr[mb][2] = Qsu[row * 68 + col + 4];
                afr[mb][3] = Qsu[(row + 8) * 68 + col + 4];
            }
            #pragma unroll
            for (int nb = 0; nb < 10; nb++) {
                int n = wn * 80 + nb * 8 + g;
                uint32_t bfr[2];
                bfr[0] = Bcu[n * 68 + ks * 8 + tig];
                bfr[1] = Bcu[n * 68 + ks * 8 + tig + 4];
                mma_tf32(cS[0][nb], afr[0], bfr);
                mma_tf32(cS[1][nb], afr[1], bfr);
            }
        }
        __syncthreads();   // Bc reads done -> pos overlay safe

        // ---- write pos scores (cols >= 192) to Ps[i][l'] (raw fp32) ----
        #pragma unroll
        for (int mb = 0; mb < 2; mb++)
            #pragma unroll
            for (int nb = 0; nb < 10; nb++) {
                int jb = wn * 80 + nb * 8;
                if (jb >= 192) {
                    int lp = jb - 192 + 2 * tig;
                    int i1 = wm * 32 + mb * 16 + g;
                    *(float2*)(Ps + i1 * 132 + lp)       = make_float2(cS[mb][nb][0], cS[mb][nb][1]);
                    *(float2*)(Ps + (i1 + 8) * 132 + lp) = make_float2(cS[mb][nb][2], cS[mb][nb][3]);
                }
            }
        __syncthreads();

        // ---- exp + skewed W (cols < 192), tf32-rounded; accumulate rowsums ----
        #pragma unroll
        for (int mb = 0; mb < 2; mb++)
            #pragma unroll
            for (int nb = 0; nb < 10; nb++) {
                int jb = wn * 80 + nb * 8;
                if (jb < 192) {
                    int j0 = jb + 2 * tig;
                    #pragma unroll
                    for (int h = 0; h < 2; h++) {
                        int i = wm * 32 + mb * 16 + g + 8 * h;
                        float s0 = cS[mb][nb][2 * h], s1 = cS[mb][nb][2 * h + 1];
                        int l0 = j0 - i;
                        float w0 = 0.f, w1 = 0.f;
                        if (l0 >= 0 && l0 < 128)
                            w0 = __uint_as_float(f2tf(__expf((s0 + Ps[i * 132 + l0]) * 0.125f)));
                        if (l0 + 1 >= 0 && l0 + 1 < 128)
                            w1 = __uint_as_float(f2tf(__expf((s1 + Ps[i * 132 + l0 + 1]) * 0.125f)));
                        rsv[mb * 2 + h] += w0 + w1;
                        *(float2*)(Ws + i * 196 + j0) = make_float2(w0, w1);
                    }
                }
            }
        __syncthreads();

        // ---- PV: O[64x64] += Ws[64x192] * Vs[192x64] ----
        #pragma unroll
        for (int ks = 0; ks < 24; ks++) {
            uint32_t afr[2][4];
            const int kk = ks * 8 + tig;
            #pragma unroll
            for (int mb = 0; mb < 2; mb++) {
                int row = wm * 32 + mb * 16 + g;
                afr[mb][0] = Wsu[row * 196 + kk];
                afr[mb][1] = Wsu[(row + 8) * 196 + kk];
                afr[mb][2] = Wsu[row * 196 + kk + 4];
                afr[mb][3] = Wsu[(row + 8) * 196 + kk + 4];
            }
            #pragma unroll
            for (int nb = 0; nb < 2; nb++) {
                int d = wn * 16 + nb * 8 + g;
                uint32_t bfr[2];
                bfr[0] = Vsu[kk * 72 + d];
                bfr[1] = Vsu[(kk + 4) * 72 + d];
                mma_tf32(cO[0][nb], afr[0], bfr);
                mma_tf32(cO[1][nb], afr[1], bfr);
            }
        }
    }

    // ---- rowsum reduction ----
    #pragma unroll
    for (int q = 0; q < 4; q++) {
        float v = rsv[q];
        v += __shfl_xor_sync(0xffffffffu, v, 1);
        v += __shfl_xor_sync(0xffffffffu, v, 2);
        if (tig == 0) {
            int i = wm * 32 + (q >> 1) * 16 + g + 8 * (q & 1);
            atomicAdd(&Rs[i], v);
        }
    }
    __syncthreads();

    // ---- normalize + store ----
    #pragma unroll
    for (int mb = 0; mb < 2; mb++) {
        int i1 = wm * 32 + mb * 16 + g;
        float inv0 = 1.f / Rs[i1];
        float inv1 = 1.f / Rs[i1 + 8];
        #pragma unroll
        for (int nb = 0; nb < 2; nb++) {
            int d = wn * 16 + nb * 8 + 2 * tig;
            float2 o0 = make_float2(cO[mb][nb][0] * inv0, cO[mb][nb][1] * inv0);
            float2 o1 = make_float2(cO[mb][nb][2] * inv1, cO[mb][nb][3] * inv1);
            *(float2*)(O + ((size_t)bh * MSEQ + m0 + i1) * DIMN + d)     = o0;
            *(float2*)(O + ((size_t)bh * MSEQ + m0 + i1 + 8) * DIMN + d) = o1;
        }
    }
}

extern "C" void kernel_launch(void* const* d_in, const int* in_sizes, int n_in,
                              void* d_out, int out_size) {
    const float* Q = (const float*)d_in[0];
    const float* K = (const float*)d_in[1];
    const float* V = (const float*)d_in[2];
    const float* P = (const float*)d_in[3];
    float* O = (float*)d_out;
    (void)n_in; (void)in_sizes; (void)out_size;

    const size_t smem_bytes = SMEM_FLOATS * sizeof(float);  // 210176 B
    cudaFuncSetAttribute(seqattn_mma_kernel,
                         cudaFuncAttributeMaxDynamicSharedMemorySize,
                         (int)smem_bytes);

    dim3 grid(MSEQ / BM, BHN);   // (16, 64)
    seqattn_mma_kernel<<<grid, 256, smem_bytes>>>(Q, K, V, P, O);
}

// round 8
// speedup vs baseline: 2.3307x; 1.7194x over previous
#include <cuda_runtime.h>
#include <cstdint>
#include <math.h>

// -------- problem shape --------
#define BHN    64
#define MSEQ   1024
#define DIMN   64
#define LSPAN  1024
#define BM     64          // query rows per CTA
#define BL     128         // l-tile width
#define RW     192         // band rect width = BM + BL
#define NT     (LSPAN / BL)
#define NTHR   512

// -------- smem strides (floats) --------
#define QS_S 68
#define KS_S 68
#define VS_S 72
#define PN_S 136
#define WS_S 200
#define OB_S 68

// -------- smem float offsets --------
#define QS_OFF 0                       // Q   [64][68]  = 4352
#define KS_OFF 4352                    // K   [192][68] = 13056
#define VS_OFF 17408                   // V   [192][72] = 13824
#define PN_OFF 31232                   // P^T nat [64][136] = 8704 ; overlay posS [64][136]
#define WS_OFF 39936                   // W skewed [64][200] = 12800
#define RS_OFF 52736                   // rowsums [64]
#define OB_OFF KS_OFF                  // O reduction buffer [64][68] (reuses K, post-loop)
#define SMEM_FLOATS 52800              // 211200 bytes

__device__ __forceinline__ uint32_t smem_u32(const void* p) {
    uint32_t a;
    asm("{ .reg .u64 t; cvta.to.shared.u64 t, %1; cvt.u32.u64 %0, t; }" : "=r"(a) : "l"(p));
    return a;
}
__device__ __forceinline__ void cp16(uint32_t dst, const void* src) {
    asm volatile("cp.async.ca.shared.global [%0], [%1], 16;" :: "r"(dst), "l"(src) : "memory");
}
#define CP_COMMIT() asm volatile("cp.async.commit_group;" ::: "memory")
#define CP_WAIT0()  asm volatile("cp.async.wait_group 0;" ::: "memory")

__device__ __forceinline__ uint32_t f2tf(float x) {
    uint32_t u;
    asm("cvt.rna.tf32.f32 %0, %1;" : "=r"(u) : "f"(x));
    return u;
}
__device__ __forceinline__ void mma_tf32(float c[4], const uint32_t a[4], const uint32_t b[2]) {
    asm volatile(
        "mma.sync.aligned.m16n8k8.row.col.f32.tf32.tf32.f32 "
        "{%0,%1,%2,%3}, {%4,%5,%6,%7}, {%8,%9}, {%0,%1,%2,%3};"
        : "+f"(c[0]), "+f"(c[1]), "+f"(c[2]), "+f"(c[3])
        : "r"(a[0]), "r"(a[1]), "r"(a[2]), "r"(a[3]), "r"(b[0]), "r"(b[1]));
}

__global__ void __launch_bounds__(NTHR, 1) seqattn_mma2_kernel(
    const float* __restrict__ Q,   // [BH, M, D]
    const float* __restrict__ K,   // [BH, M+L, D]
    const float* __restrict__ V,   // [BH, M+L, D]
    const float* __restrict__ P,   // [D, L]
    float* __restrict__ O)         // [BH, M, D]
{
    extern __shared__ float sm[];
    const uint32_t sb = smem_u32(sm);

    float*          Qs  = sm + QS_OFF;
    float*          Vs  = sm + VS_OFF;
    float*          posS= sm + PN_OFF;   // overlay of P-natural after S GEMM
    float*          Ws  = sm + WS_OFF;
    float*          Rs  = sm + RS_OFF;
    const uint32_t* Qsu = (const uint32_t*)Qs;
    const uint32_t* Ksu = (const uint32_t*)(sm + KS_OFF);
    const uint32_t* PNu = (const uint32_t*)(sm + PN_OFF);
    const uint32_t* Vsu = (const uint32_t*)Vs;
    const uint32_t* Wsu = (const uint32_t*)Ws;

    const int tid  = threadIdx.x;
    const int w    = tid >> 5;
    const int lane = tid & 31;
    const int g    = lane >> 2;      // 0..7
    const int tig  = lane & 3;       // 0..3

    // S GEMM / exp layout: 2 (m) x 8 (n) warps
    const int wm = w >> 3;           // 0..1 : 32 rows each
    const int wn = w & 7;            // 0..7 : 24 content cols, 16 pos cols each
    // PV layout: 4 k-groups x (2 x 2)
    const int kg  = w & 3;           // k-group: 48 k each
    const int ww  = w >> 2;          // 0..3
    const int wmP = ww >> 1;         // rows 32 each
    const int wnP = ww & 1;          // cols 32 each

    const int bh = blockIdx.y;
    const int m0 = blockIdx.x * BM;

    const float* Qg = Q + ((size_t)bh * MSEQ + m0) * DIMN;
    const float* Kg = K + (size_t)bh * (MSEQ + LSPAN) * DIMN;
    const float* Vg = V + (size_t)bh * (MSEQ + LSPAN) * DIMN;

    // ---- preamble: Q (rna cvt), Rs init, prefetch K/P tile 0, V tile 0 ----
    #pragma unroll
    for (int p = 0; p < 2; p++) {
        int idx = p * NTHR + tid;
        int r = idx >> 4, c = idx & 15;
        float4 v = *(const float4*)(Qg + (size_t)r * DIMN + c * 4);
        uint4 u = make_uint4(f2tf(v.x), f2tf(v.y), f2tf(v.z), f2tf(v.w));
        *(uint4*)(Qs + r * QS_S + c * 4) = u;
    }
    if (tid < 64) Rs[tid] = 0.f;

    {
        const int jg0 = m0;
        #pragma unroll
        for (int p = 0; p < 6; p++) {   // K tile 0
            int idx = p * NTHR + tid;
            int r = idx >> 4, c = idx & 15;
            cp16(sb + (uint32_t)(KS_OFF + r * KS_S + c * 4) * 4u,
                 Kg + (size_t)(jg0 + r) * DIMN + c * 4);
        }
        #pragma unroll
        for (int p = 0; p < 4; p++) {   // P tile 0 (natural [d][l])
            int idx = p * NTHR + tid;
            int d = idx >> 5, c = idx & 31;
            cp16(sb + (uint32_t)(PN_OFF + d * PN_S + c * 4) * 4u,
                 P + (size_t)d * LSPAN + c * 4);
        }
        CP_COMMIT();
        #pragma unroll
        for (int p = 0; p < 6; p++) {   // V tile 0 (rna cvt)
            int idx = p * NTHR + tid;
            int r = idx >> 4, c = idx & 15;
            float4 v = *(const float4*)(Vg + (size_t)(jg0 + r) * DIMN + c * 4);
            uint4 u = make_uint4(f2tf(v.x), f2tf(v.y), f2tf(v.z), f2tf(v.w));
            *(uint4*)(Vs + r * VS_S + c * 4) = u;
        }
        CP_WAIT0();
    }
    __syncthreads();

    float cO[2][4][4];
    #pragma unroll
    for (int a = 0; a < 2; a++)
        #pragma unroll
        for (int b = 0; b < 4; b++)
            #pragma unroll
            for (int c = 0; c < 4; c++) cO[a][b][c] = 0.f;
    float rsv[4] = {0.f, 0.f, 0.f, 0.f};

    for (int lt = 0; lt < NT; lt++) {
        // ================= S GEMM: content 64x192 + pos 64x128 =================
        float cC[2][3][4], cP[2][2][4];
        #pragma unroll
        for (int mb = 0; mb < 2; mb++) {
            #pragma unroll
            for (int nb = 0; nb < 3; nb++)
                #pragma unroll
                for (int c = 0; c < 4; c++) cC[mb][nb][c] = 0.f;
            #pragma unroll
            for (int nb = 0; nb < 2; nb++)
                #pragma unroll
                for (int c = 0; c < 4; c++) cP[mb][nb][c] = 0.f;
        }

        #pragma unroll
        for (int ks = 0; ks < 8; ks++) {
            const int col = ks * 8 + tig;
            uint32_t a[2][4];
            #pragma unroll
            for (int mb = 0; mb < 2; mb++) {
                int row = wm * 32 + mb * 16 + g;
                a[mb][0] = Qsu[row * QS_S + col];
                a[mb][1] = Qsu[(row + 8) * QS_S + col];
                a[mb][2] = Qsu[row * QS_S + col + 4];
                a[mb][3] = Qsu[(row + 8) * QS_S + col + 4];
            }
            #pragma unroll
            for (int nb = 0; nb < 3; nb++) {
                int n = wn * 24 + nb * 8 + g;
                uint32_t b[2];
                b[0] = Ksu[n * KS_S + col];
                b[1] = Ksu[n * KS_S + col + 4];
                mma_tf32(cC[0][nb], a[0], b);
                mma_tf32(cC[1][nb], a[1], b);
            }
            #pragma unroll
            for (int nb = 0; nb < 2; nb++) {
                int n = wn * 16 + nb * 8 + g;
                uint32_t b[2];
                b[0] = PNu[col * PN_S + n];
                b[1] = PNu[(col + 4) * PN_S + n];
                mma_tf32(cP[0][nb], a[0], b);
                mma_tf32(cP[1][nb], a[1], b);
            }
        }
        __syncthreads();   // K/P^T reads done

        // prefetch next K (dst: Ks, now free)
        if (lt < NT - 1) {
            const int jg0n = m0 + (lt + 1) * BL;
            #pragma unroll
            for (int p = 0; p < 6; p++) {
                int idx = p * NTHR + tid;
                int r = idx >> 4, c = idx & 15;
                cp16(sb + (uint32_t)(KS_OFF + r * KS_S + c * 4) * 4u,
                     Kg + (size_t)(jg0n + r) * DIMN + c * 4);
            }
            CP_COMMIT();
        }

        // ---- write pos scores skand: posS[i][l] (overlays P^T region) ----
        #pragma unroll
        for (int mb = 0; mb < 2; mb++)
            #pragma unroll
            for (int nb = 0; nb < 2; nb++) {
                int lp = wn * 16 + nb * 8 + 2 * tig;
                int i1 = wm * 32 + mb * 16 + g;
                *(float2*)(posS + i1 * PN_S + lp)       = make_float2(cP[mb][nb][0], cP[mb][nb][1]);
                *(float2*)(posS + (i1 + 8) * PN_S + lp) = make_float2(cP[mb][nb][2], cP[mb][nb][3]);
            }
        __syncthreads();   // posS visible

        // ---- exp + skewed W (tf32-rounded) + rowsums ----
        #pragma unroll
        for (int mb = 0; mb < 2; mb++)
            #pragma unroll
            for (int nb = 0; nb < 3; nb++) {
                int j0 = wn * 24 + nb * 8 + 2 * tig;
                #pragma unroll
                for (int h = 0; h < 2; h++) {
                    int i = wm * 32 + mb * 16 + g + 8 * h;
                    float s0 = cC[mb][nb][2 * h], s1 = cC[mb][nb][2 * h + 1];
                    int l0 = j0 - i;
                    float w0 = 0.f, w1 = 0.f;
                    if (l0 >= 0 && l0 < 128)
                        w0 = __uint_as_float(f2tf(__expf((s0 + posS[i * PN_S + l0]) * 0.125f)));
                    if (l0 + 1 >= 0 && l0 + 1 < 128)
                        w1 = __uint_as_float(f2tf(__expf((s1 + posS[i * PN_S + l0 + 1]) * 0.125f)));
                    rsv[mb * 2 + h] += w0 + w1;
                    *(float2*)(Ws + i * WS_S + j0) = make_float2(w0, w1);
                }
            }
        __syncthreads();   // posS reads done, Ws visible

        // prefetch next P (dst: PN region, posS now dead)
        if (lt < NT - 1) {
            #pragma unroll
            for (int p = 0; p < 4; p++) {
                int idx = p * NTHR + tid;
                int d = idx >> 5, c = idx & 31;
                cp16(sb + (uint32_t)(PN_OFF + d * PN_S + c * 4) * 4u,
                     P + (size_t)d * LSPAN + (lt + 1) * BL + c * 4);
            }
            CP_COMMIT();
        }

        // ================= PV: cO += Ws[64x192] * Vs[192x64] (k-split x4) =====
        #pragma unroll
        for (int kk = 0; kk < 6; kk++) {
            const int kb = kg * 48 + kk * 8 + tig;
            uint32_t a[2][4];
            #pragma unroll
            for (int mb = 0; mb < 2; mb++) {
                int row = wmP * 32 + mb * 16 + g;
                a[mb][0] = Wsu[row * WS_S + kb];
                a[mb][1] = Wsu[(row + 8) * WS_S + kb];
                a[mb][2] = Wsu[row * WS_S + kb + 4];
                a[mb][3] = Wsu[(row + 8) * WS_S + kb + 4];
            }
            #pragma unroll
            for (int nb = 0; nb < 4; nb++) {
                int d = wnP * 32 + nb * 8 + g;
                uint32_t b[2];
                b[0] = Vsu[kb * VS_S + d];
                b[1] = Vsu[(kb + 4) * VS_S + d];
                mma_tf32(cO[0][nb], a[0], b);
                mma_tf32(cO[1][nb], a[1], b);
            }
        }
        CP_WAIT0();
        __syncthreads();   // Vs/Ws reads done; K/P arrived

        // ---- load next V (rna cvt) ----
        if (lt < NT - 1) {
            const int jg0n = m0 + (lt + 1) * BL;
            #pragma unroll
            for (int p = 0; p < 6; p++) {
                int idx = p * NTHR + tid;
                int r = idx >> 4, c = idx & 15;
                float4 v = *(const float4*)(Vg + (size_t)(jg0n + r) * DIMN + c * 4);
                uint4 u = make_uint4(f2tf(v.x), f2tf(v.y), f2tf(v.z), f2tf(v.w));
                *(uint4*)(Vs + r * VS_S + c * 4) = u;
            }
            __syncthreads();
        }
    }

    // ---- rowsum reduction ----
    #pragma unroll
    for (int q = 0; q < 4; q++) {
        float v = rsv[q];
        v += __shfl_xor_sync(0xffffffffu, v, 1);
        v += __shfl_xor_sync(0xffffffffu, v, 2);
        if (tig == 0) {
            int i = wm * 32 + (q >> 1) * 16 + g + 8 * (q & 1);
            atomicAdd(&Rs[i], v);
        }
    }
    __syncthreads();   // all PV done everywhere; K buffer reusable as Obuf

    // ---- k-group reduction of cO into Obuf ----
    float* Ob = sm + OB_OFF;
    #pragma unroll
    for (int step = 0; step < 4; step++) {
        if (kg == step) {
            #pragma unroll
            for (int mb = 0; mb < 2; mb++)
                #pragma unroll
                for (int nb = 0; nb < 4; nb++) {
                    int row = wmP * 32 + mb * 16 + g;
                    int col = wnP * 32 + nb * 8 + 2 * tig;
                    if (step == 0) {
                        *(float2*)(Ob + row * OB_S + col)       = make_float2(cO[mb][nb][0], cO[mb][nb][1]);
                        *(float2*)(Ob + (row + 8) * OB_S + col) = make_float2(cO[mb][nb][2], cO[mb][nb][3]);
                    } else {
                        float2 p0 = *(float2*)(Ob + row * OB_S + col);
                        float2 p1 = *(float2*)(Ob + (row + 8) * OB_S + col);
                        p0.x += cO[mb][nb][0]; p0.y += cO[mb][nb][1];
                        p1.x += cO[mb][nb][2]; p1.y += cO[mb][nb][3];
                        *(float2*)(Ob + row * OB_S + col)       = p0;
                        *(float2*)(Ob + (row + 8) * OB_S + col) = p1;
                    }
                }
        }
        __syncthreads();
    }

    // ---- normalize + store ----
    {
        int row = tid >> 3;
        int c8  = (tid & 7) * 8;
        float inv = 1.f / Rs[row];
        float4 o0 = *(float4*)(Ob + row * OB_S + c8);
        float4 o1 = *(float4*)(Ob + row * OB_S + c8 + 4);
        o0.x *= inv; o0.y *= inv; o0.z *= inv; o0.w *= inv;
        o1.x *= inv; o1.y *= inv; o1.z *= inv; o1.w *= inv;
        float* orow = O + ((size_t)bh * MSEQ + m0 + row) * DIMN + c8;
        *(float4*)(orow)     = o0;
        *(float4*)(orow + 4) = o1;
    }
}

extern "C" void kernel_launch(void* const* d_in, const int* in_sizes, int n_in,
                              void* d_out, int out_size) {
    const float* Q = (const float*)d_in[0];
    const float* K = (const float*)d_in[1];
    const float* V = (const float*)d_in[2];
    const float* P = (const float*)d_in[3];
    float* O = (float*)d_out;
    (void)n_in; (void)in_sizes; (void)out_size;

    const size_t smem_bytes = SMEM_FLOATS * sizeof(float);  // 211200 B
    cudaFuncSetAttribute(seqattn_mma2_kernel,
                         cudaFuncAttributeMaxDynamicSharedMemorySize,
                         (int)smem_bytes);

    dim3 grid(MSEQ / BM, BHN);   // (16, 64)
    seqattn_mma2_kernel<<<grid, NTHR, smem_bytes>>>(Q, K, V, P, O);
}

// round 9
// speedup vs baseline: 3.7659x; 1.6157x over previous
#include <cuda_runtime.h>
#include <cuda_fp16.h>
#include <cstdint>
#include <math.h>

// -------- problem shape --------
#define BHN    64
#define MSEQ   1024
#define DIMN   64
#define LSPAN  1024
#define KVROWS (MSEQ + LSPAN)
#define BM     64
#define BL     128
#define RW     192
#define NT     (LSPAN / BL)
#define NTHR   512

// -------- fp16 preconverted operands (device scratch; allocation-free) --------
__device__ __half g_Qh [(size_t)BHN * MSEQ  * DIMN];   //  8 MB, [bh][i][d]
__device__ __half g_Kh [(size_t)BHN * KVROWS * DIMN];  // 16 MB, [bh][j][d]
__device__ __half g_VTh[(size_t)BHN * DIMN * KVROWS];  // 16 MB, [bh][d][j]
__device__ __half g_PTh[(size_t)LSPAN * DIMN];         // 128 KB, [l][d]

// -------- smem byte offsets --------
#define QS_B 0        // Q    [64][72]  f16 =  9216
#define KS_B 9216     // K    [192][72] f16 = 27648
#define VT_B 36864    // V^T  [64][200] f16 = 25600
#define PT_B 62464    // P^T  [128][72] f16 = 18432
#define WS_B 80896    // W    [64][200] f16 = 25600
#define PS_B 106496   // posS [64][132] f32 = 33792
#define RS_B 140288   // rowsums [64]   f32 =   256
#define OB_B KS_B     // O-reduce [64][68] f32 (post-loop, reuses K)
#define SMEM_BYTES 140544

// -------- b32 strides --------
#define QS2 36
#define KS2 36
#define PT2 36
#define VT2 100
#define WS2 100
#define PSF 132
#define OBF 68

__device__ __forceinline__ uint32_t smem_u32(const void* p) {
    uint32_t a;
    asm("{ .reg .u64 t; cvta.to.shared.u64 t, %1; cvt.u32.u64 %0, t; }" : "=r"(a) : "l"(p));
    return a;
}
__device__ __forceinline__ void cp16(uint32_t dst, const void* src) {
    asm volatile("cp.async.ca.shared.global [%0], [%1], 16;" :: "r"(dst), "l"(src) : "memory");
}
#define CP_COMMIT() asm volatile("cp.async.commit_group;" ::: "memory")
#define CP_WAIT0()  asm volatile("cp.async.wait_group 0;" ::: "memory")
#define CP_WAIT1()  asm volatile("cp.async.wait_group 1;" ::: "memory")

__device__ __forceinline__ void mma_f16(float c[4], const uint32_t a[4], const uint32_t b[2]) {
    asm volatile(
        "mma.sync.aligned.m16n8k16.row.col.f32.f16.f16.f32 "
        "{%0,%1,%2,%3}, {%4,%5,%6,%7}, {%8,%9}, {%0,%1,%2,%3};"
        : "+f"(c[0]), "+f"(c[1]), "+f"(c[2]), "+f"(c[3])
        : "r"(a[0]), "r"(a[1]), "r"(a[2]), "r"(a[3]), "r"(b[0]), "r"(b[1]));
}

// ================= pre-pass: f32 -> f16 (rna), V transposed =================
__global__ void prep_qkv(const float* __restrict__ Q, const float* __restrict__ K,
                         const float* __restrict__ V) {
    const int x = blockIdx.x, bh = blockIdx.y, tid = threadIdx.x;
    if (x < 16) {
        size_t base = ((size_t)bh * MSEQ + x * 64) * DIMN;
        #pragma unroll
        for (int p = 0; p < 4; p++) {
            int idx = p * 256 + tid;
            float4 v = *(const float4*)(Q + base + (size_t)idx * 4);
            __half2 h0 = __floats2half2_rn(v.x, v.y);
            __half2 h1 = __floats2half2_rn(v.z, v.w);
            *(uint2*)(&g_Qh[base + (size_t)idx * 4]) =
                make_uint2(*(uint32_t*)&h0, *(uint32_t*)&h1);
        }
    } else if (x < 48) {
        size_t base = ((size_t)bh * KVROWS + (x - 16) * 64) * DIMN;
        #pragma unroll
        for (int p = 0; p < 4; p++) {
            int idx = p * 256 + tid;
            float4 v = *(const float4*)(K + base + (size_t)idx * 4);
            __half2 h0 = __floats2half2_rn(v.x, v.y);
            __half2 h1 = __floats2half2_rn(v.z, v.w);
            *(uint2*)(&g_Kh[base + (size_t)idx * 4]) =
                make_uint2(*(uint32_t*)&h0, *(uint32_t*)&h1);
        }
    } else {
        __shared__ float ts[64][65];   // [j][d]
        const int j0 = (x - 48) * 64;
        size_t base = ((size_t)bh * KVROWS + j0) * DIMN;
        #pragma unroll
        for (int p = 0; p < 16; p++) {
            int idx = p * 256 + tid;
            ts[idx >> 6][idx & 63] = V[base + idx];
        }
        __syncthreads();
        const int d = tid >> 2, jq = (tid & 3) * 16;
        uint32_t u[8];
        #pragma unroll
        for (int q = 0; q < 8; q++) {
            __half2 h = __floats2half2_rn(ts[jq + 2 * q][d], ts[jq + 2 * q + 1][d]);
            u[q] = *(uint32_t*)&h;
        }
        __half* dst = &g_VTh[((size_t)bh * DIMN + d) * KVROWS + j0 + jq];
        *(uint4*)dst       = make_uint4(u[0], u[1], u[2], u[3]);
        *(uint4*)(dst + 8) = make_uint4(u[4], u[5], u[6], u[7]);
    }
}

__global__ void prep_pt(const float* __restrict__ P) {
    __shared__ float ts[64][65];   // [l][d]
    const int l0 = blockIdx.x * 64, tid = threadIdx.x;
    #pragma unroll
    for (int p = 0; p < 16; p++) {
        int idx = p * 256 + tid;
        int d = idx >> 6, lq = idx & 63;
        ts[lq][d] = P[(size_t)d * LSPAN + l0 + lq];
    }
    __syncthreads();
    const int lq = tid >> 2, dq = (tid & 3) * 16;
    uint32_t u[8];
    #pragma unroll
    for (int q = 0; q < 8; q++) {
        __half2 h = __floats2half2_rn(ts[lq][dq + 2 * q], ts[lq][dq + 2 * q + 1]);
        u[q] = *(uint32_t*)&h;
    }
    __half* dst = &g_PTh[(size_t)(l0 + lq) * DIMN + dq];
    *(uint4*)dst       = make_uint4(u[0], u[1], u[2], u[3]);
    *(uint4*)(dst + 8) = make_uint4(u[4], u[5], u[6], u[7]);
}

// ================= main kernel =================
__global__ void __launch_bounds__(NTHR, 1) seqattn_f16_kernel(float* __restrict__ O) {
    extern __shared__ char sm[];
    const uint32_t sb = smem_u32(sm);

    const uint32_t* Qsu = (const uint32_t*)(sm + QS_B);
    const uint32_t* Ksu = (const uint32_t*)(sm + KS_B);
    const uint32_t* Vtu = (const uint32_t*)(sm + VT_B);
    const uint32_t* Ptu = (const uint32_t*)(sm + PT_B);
    uint32_t*       Wsu = (uint32_t*)(sm + WS_B);
    float*          psf = (float*)(sm + PS_B);
    float*          Rs  = (float*)(sm + RS_B);

    const int tid  = threadIdx.x;
    const int w    = tid >> 5;
    const int lane = tid & 31;
    const int g    = lane >> 2;
    const int tig  = lane & 3;

    // S GEMM / exp layout: 2m x 8n warps
    const int wm = w >> 3;
    const int wn = w & 7;
    // PV layout: 4 k-groups x (2m x 2n)
    const int kg  = w & 3;
    const int ww  = w >> 2;
    const int wmP = ww >> 1;
    const int wnP = ww & 1;

    const int bh = blockIdx.y;
    const int m0 = blockIdx.x * BM;

    const __half* Qh  = g_Qh  + ((size_t)bh * MSEQ + m0) * DIMN;
    const __half* Kh  = g_Kh  + (size_t)bh * KVROWS * DIMN;
    const __half* VTh = g_VTh + (size_t)bh * DIMN * KVROWS;

    // ---- preamble: prefetch Q, K(0), PT(0) (group A) then V(0) (group B) ----
    {
        int r = tid >> 3, c = tid & 7;
        cp16(sb + QS_B + (uint32_t)(r * 72 + c * 8) * 2u, Qh + (size_t)r * DIMN + c * 8);
        #pragma unroll
        for (int p = 0; p < 3; p++) {   // K(0): 192 rows x 8 chunks
            int idx = p * NTHR + tid;
            int kr = idx >> 3, kc = idx & 7;
            cp16(sb + KS_B + (uint32_t)(kr * 72 + kc * 8) * 2u,
                 Kh + (size_t)(m0 + kr) * DIMN + kc * 8);
        }
        #pragma unroll
        for (int p = 0; p < 2; p++) {   // PT(0): 128 rows x 8 chunks
            int idx = p * NTHR + tid;
            int pr = idx >> 3, pc = idx & 7;
            cp16(sb + PT_B + (uint32_t)(pr * 72 + pc * 8) * 2u,
                 g_PTh + (size_t)pr * DIMN + pc * 8);
        }
        CP_COMMIT();
        #pragma unroll
        for (int p = 0; p < 3; p++) {   // V(0): 64 rows x 24 chunks
            int idx = p * NTHR + tid;
            int d = idx / 24, c24 = idx % 24;
            cp16(sb + VT_B + (uint32_t)(d * 200 + c24 * 8) * 2u,
                 VTh + (size_t)d * KVROWS + m0 + c24 * 8);
        }
        CP_COMMIT();
    }
    if (tid < 64) Rs[tid] = 0.f;

    float cO[2][4][4];
    #pragma unroll
    for (int a = 0; a < 2; a++)
        #pragma unroll
        for (int b = 0; b < 4; b++)
            #pragma unroll
            for (int c = 0; c < 4; c++) cO[a][b][c] = 0.f;
    float rsv[4] = {0.f, 0.f, 0.f, 0.f};

    for (int lt = 0; lt < NT; lt++) {
        CP_WAIT1();        // Q/K/PT of this tile arrived (V may be in flight)
        __syncthreads();

        // ========== S GEMM: content 64x192 + pos 64x128 (fp16, k=64) ==========
        float cC[2][3][4], cP[2][2][4];
        #pragma unroll
        for (int mb = 0; mb < 2; mb++) {
            #pragma unroll
            for (int nb = 0; nb < 3; nb++)
                #pragma unroll
                for (int c = 0; c < 4; c++) cC[mb][nb][c] = 0.f;
            #pragma unroll
            for (int nb = 0; nb < 2; nb++)
                #pragma unroll
                for (int c = 0; c < 4; c++) cP[mb][nb][c] = 0.f;
        }

        #pragma unroll
        for (int ks = 0; ks < 4; ks++) {
            const int c2 = ks * 8 + tig;
            uint32_t a[2][4];
            #pragma unroll
            for (int mb = 0; mb < 2; mb++) {
                int row = wm * 32 + mb * 16 + g;
                a[mb][0] = Qsu[row * QS2 + c2];
                a[mb][1] = Qsu[(row + 8) * QS2 + c2];
                a[mb][2] = Qsu[row * QS2 + c2 + 4];
                a[mb][3] = Qsu[(row + 8) * QS2 + c2 + 4];
            }
            #pragma unroll
            for (int nb = 0; nb < 2; nb++) {       // pos first
                int n = wn * 16 + nb * 8 + g;
                uint32_t b[2] = { Ptu[n * PT2 + c2], Ptu[n * PT2 + c2 + 4] };
                mma_f16(cP[0][nb], a[0], b);
                mma_f16(cP[1][nb], a[1], b);
            }
            #pragma unroll
            for (int nb = 0; nb < 3; nb++) {       // content
                int n = wn * 24 + nb * 8 + g;
                uint32_t b[2] = { Ksu[n * KS2 + c2], Ksu[n * KS2 + c2 + 4] };
                mma_f16(cC[0][nb], a[0], b);
                mma_f16(cC[1][nb], a[1], b);
            }
        }

        // ---- pos scores -> dedicated posS buffer (no pre-barrier needed) ----
        #pragma unroll
        for (int mb = 0; mb < 2; mb++)
            #pragma unroll
            for (int nb = 0; nb < 2; nb++) {
                int lp = wn * 16 + nb * 8 + 2 * tig;
                int i1 = wm * 32 + mb * 16 + g;
                *(float2*)(psf + i1 * PSF + lp)       = make_float2(cP[mb][nb][0], cP[mb][nb][1]);
                *(float2*)(psf + (i1 + 8) * PSF + lp) = make_float2(cP[mb][nb][2], cP[mb][nb][3]);
            }
        __syncthreads();   // sync1: posS visible; Ks/Pts/Qs reads done

        // prefetch next K + PT (one group)
        if (lt < NT - 1) {
            const int jg0n = m0 + (lt + 1) * BL;
            #pragma unroll
            for (int p = 0; p < 3; p++) {
                int idx = p * NTHR + tid;
                int kr = idx >> 3, kc = idx & 7;
                cp16(sb + KS_B + (uint32_t)(kr * 72 + kc * 8) * 2u,
                     Kh + (size_t)(jg0n + kr) * DIMN + kc * 8);
            }
            #pragma unroll
            for (int p = 0; p < 2; p++) {
                int idx = p * NTHR + tid;
                int pr = idx >> 3, pc = idx & 7;
                cp16(sb + PT_B + (uint32_t)(pr * 72 + pc * 8) * 2u,
                     g_PTh + (size_t)((lt + 1) * BL + pr) * DIMN + pc * 8);
            }
            CP_COMMIT();
        }

        // ---- exp + banded W (f16x2) + rowsums ----
        #pragma unroll
        for (int mb = 0; mb < 2; mb++)
            #pragma unroll
            for (int nb = 0; nb < 3; nb++) {
                int j0 = wn * 24 + nb * 8 + 2 * tig;
                #pragma unroll
                for (int h = 0; h < 2; h++) {
                    int i = wm * 32 + mb * 16 + g + 8 * h;
                    float s0 = cC[mb][nb][2 * h], s1 = cC[mb][nb][2 * h + 1];
                    int l0 = j0 - i;
                    float w0 = 0.f, w1 = 0.f;
                    if (l0 >= 0 && l0 < 128)
                        w0 = __expf((s0 + psf[i * PSF + l0]) * 0.125f);
                    if (l0 + 1 >= 0 && l0 + 1 < 128)
                        w1 = __expf((s1 + psf[i * PSF + l0 + 1]) * 0.125f);
                    __half2 hw = __floats2half2_rn(w0, w1);
                    float2 bk = __half22float2(hw);
                    rsv[mb * 2 + h] += bk.x + bk.y;
                    Wsu[i * WS2 + (j0 >> 1)] = *(uint32_t*)&hw;
                }
            }

        // V(t) must be resident before PV
        if (lt < NT - 1) { CP_WAIT1(); } else { CP_WAIT0(); }
        __syncthreads();   // sync2: Ws visible, V visible

        // ========== PV: cO += W[64x192] * V[192x64] (k-split x4) ==========
        #pragma unroll
        for (int kk = 0; kk < 3; kk++) {
            const int kb2 = kg * 24 + kk * 8 + tig;
            uint32_t a[2][4];
            #pragma unroll
            for (int mb = 0; mb < 2; mb++) {
                int row = wmP * 32 + mb * 16 + g;
                a[mb][0] = Wsu[row * WS2 + kb2];
                a[mb][1] = Wsu[(row + 8) * WS2 + kb2];
                a[mb][2] = Wsu[row * WS2 + kb2 + 4];
                a[mb][3] = Wsu[(row + 8) * WS2 + kb2 + 4];
            }
            #pragma unroll
            for (int nb = 0; nb < 4; nb++) {
                int d = wnP * 32 + nb * 8 + g;
                uint32_t b[2] = { Vtu[d * VT2 + kb2], Vtu[d * VT2 + kb2 + 4] };
                mma_f16(cO[0][nb], a[0], b);
                mma_f16(cO[1][nb], a[1], b);
            }
        }
        __syncthreads();   // sync3: Vts reads done

        // prefetch next V
        if (lt < NT - 1) {
            const int jg0n = m0 + (lt + 1) * BL;
            #pragma unroll
            for (int p = 0; p < 3; p++) {
                int idx = p * NTHR + tid;
                int d = idx / 24, c24 = idx % 24;
                cp16(sb + VT_B + (uint32_t)(d * 200 + c24 * 8) * 2u,
                     VTh + (size_t)d * KVROWS + jg0n + c24 * 8);
            }
            CP_COMMIT();
        }
    }

    // ---- rowsum reduction ----
    #pragma unroll
    for (int q = 0; q < 4; q++) {
        float v = rsv[q];
        v += __shfl_xor_sync(0xffffffffu, v, 1);
        v += __shfl_xor_sync(0xffffffffu, v, 2);
        if (tig == 0) {
            int i = wm * 32 + (q >> 1) * 16 + g + 8 * (q & 1);
            atomicAdd(&Rs[i], v);
        }
    }
    __syncthreads();

    // ---- k-group reduction of cO into Ob (reuses K region) ----
    float* Ob = (float*)(sm + OB_B);
    #pragma unroll
    for (int step = 0; step < 4; step++) {
        if (kg == step) {
            #pragma unroll
            for (int mb = 0; mb < 2; mb++)
                #pragma unroll
                for (int nb = 0; nb < 4; nb++) {
                    int row = wmP * 32 + mb * 16 + g;
                    int col = wnP * 32 + nb * 8 + 2 * tig;
                    if (step == 0) {
                        *(float2*)(Ob + row * OBF + col)       = make_float2(cO[mb][nb][0], cO[mb][nb][1]);
                        *(float2*)(Ob + (row + 8) * OBF + col) = make_float2(cO[mb][nb][2], cO[mb][nb][3]);
                    } else {
                        float2 p0 = *(float2*)(Ob + row * OBF + col);
                        float2 p1 = *(float2*)(Ob + (row + 8) * OBF + col);
                        p0.x += cO[mb][nb][0]; p0.y += cO[mb][nb][1];
                        p1.x += cO[mb][nb][2]; p1.y += cO[mb][nb][3];
                        *(float2*)(Ob + row * OBF + col)       = p0;
                        *(float2*)(Ob + (row + 8) * OBF + col) = p1;
                    }
                }
        }
        __syncthreads();
    }

    // ---- normalize + store ----
    {
        int row = tid >> 3;
        int c8  = (tid & 7) * 8;
        float inv = 1.f / Rs[row];
        float4 o0 = *(float4*)(Ob + row * OBF + c8);
        float4 o1 = *(float4*)(Ob + row * OBF + c8 + 4);
        o0.x *= inv; o0.y *= inv; o0.z *= inv; o0.w *= inv;
        o1.x *= inv; o1.y *= inv; o1.z *= inv; o1.w *= inv;
        float* orow = O + ((size_t)bh * MSEQ + m0 + row) * DIMN + c8;
        *(float4*)(orow)     = o0;
        *(float4*)(orow + 4) = o1;
    }
}

extern "C" void kernel_launch(void* const* d_in, const int* in_sizes, int n_in,
                              void* d_out, int out_size) {
    const float* Q = (const float*)d_in[0];
    const float* K = (const float*)d_in[1];
    const float* V = (const float*)d_in[2];
    const float* P = (const float*)d_in[3];
    float* O = (float*)d_out;
    (void)n_in; (void)in_sizes; (void)out_size;

    // pre-pass: f32 -> f16 (rna), V and P transposed
    prep_qkv<<<dim3(80, BHN), 256>>>(Q, K, V);
    prep_pt<<<16, 256>>>(P);

    cudaFuncSetAttribute(seqattn_f16_kernel,
                         cudaFuncAttributeMaxDynamicSharedMemorySize, SMEM_BYTES);
    dim3 grid(MSEQ / BM, BHN);   // (16, 64)
    seqattn_f16_kernel<<<grid, NTHR, SMEM_BYTES>>>(O);
}